// round 7
// baseline (speedup 1.0000x reference)
#include <cuda_runtime.h>
#include <cuda_fp16.h>
#include <cstdint>

// ---------------------------------------------------------------------------
// TriXLinear (sm_103 baseline PTX; tensor path = mma.sync m16n8k16 f16).
//   out = (x @ sign(W)^T) * scales * gate_mask
// x -> fp16 (norm rel err ~2.1e-4), W -> +-1 fp16 (exact). Gated-row GEMM.
// R7: block 256x128 (BM=256) halves LTS traffic (2.0GB -> 1.0GB); GEMM was
// measured at the LTS cap. 256 threads, 8 warps (4Mx2N), warp 64x64,
// 3-stage cp.async.bulk + full/empty mbarrier pipeline, 1 CTA/SM.
// ---------------------------------------------------------------------------

#define MDIM 4096
#define NDIM 4096
#define KDIM 4096

#define NKT 64                         // K stages (64 fp16 = 128B rows)
#define STAGES 3
#define STAGE_BYTES 49152              // A 32K (2 chunks) + B 16K
#define SMEM_SC 64                     // scales cache at byte 64 (512B)
#define SMEM_ST 1024
#define SMEM_TOTAL (SMEM_ST + STAGES * STAGE_BYTES)   // 148480 -> 1 CTA/SM
// mbarriers: full[s] at sb+8s, empty[s] at sb+24+8s  (s = 0..2)

// ------------------------------- scratch -----------------------------------
__device__ __align__(1024) unsigned char g_Wt[(size_t)32 * 1024 * 1024];
__device__ __align__(1024) unsigned char g_At[(size_t)128 * 1024 * 1024];
__device__ int g_cnt[4];
__device__ int g_rows[4][MDIM];

// ------------------------------ PTX helpers --------------------------------
__device__ __forceinline__ uint32_t smem_u32(const void* p) {
    uint32_t a;
    asm("{ .reg .u64 t; cvta.to.shared.u64 t, %1; cvt.u32.u64 %0, t; }"
        : "=r"(a) : "l"(p));
    return a;
}
__device__ __forceinline__ uint32_t elect_one() {
    uint32_t p;
    asm volatile("{ .reg .pred p; elect.sync _|p, 0xFFFFFFFF; selp.b32 %0,1,0,p; }"
                 : "=r"(p));
    return p;
}
__device__ __forceinline__ void mbar_init(uint32_t mb, uint32_t cnt) {
    asm volatile("mbarrier.init.shared.b64 [%0], %1;" :: "r"(mb), "r"(cnt) : "memory");
}
__device__ __forceinline__ void mbar_expect_tx(uint32_t mb, uint32_t bytes) {
    asm volatile("mbarrier.arrive.expect_tx.shared.b64 _, [%0], %1;"
                 :: "r"(mb), "r"(bytes) : "memory");
}
__device__ __forceinline__ void mbar_arrive(uint32_t mb) {
    asm volatile("mbarrier.arrive.shared.b64 _, [%0];" :: "r"(mb) : "memory");
}
__device__ __forceinline__ void mbar_wait(uint32_t mb, uint32_t parity) {
    asm volatile(
        "{\n\t.reg .pred P;\n\t"
        "WL_%=:\n\t"
        "mbarrier.try_wait.parity.acquire.cta.shared::cta.b64 P, [%0], %1, 0x989680;\n\t"
        "@P bra.uni WD_%=;\n\t"
        "bra.uni WL_%=;\n\t"
        "WD_%=:\n\t}"
        :: "r"(mb), "r"(parity) : "memory");
}
__device__ __forceinline__ void bulk_g2s(uint32_t dst, const void* src,
                                         uint32_t bytes, uint32_t mb) {
    asm volatile(
        "cp.async.bulk.shared::cta.global.mbarrier::complete_tx::bytes "
        "[%0], [%1], %2, [%3];"
        :: "r"(dst), "l"(src), "r"(bytes), "r"(mb) : "memory");
}
__device__ __forceinline__ void ldm_x4(uint32_t* r, uint32_t addr) {
    asm volatile("ldmatrix.sync.aligned.m8n8.x4.shared.b16 {%0,%1,%2,%3}, [%4];"
                 : "=r"(r[0]), "=r"(r[1]), "=r"(r[2]), "=r"(r[3]) : "r"(addr));
}
__device__ __forceinline__ void hmma(float* c, const uint32_t* a,
                                     uint32_t b0, uint32_t b1) {
    asm volatile(
        "mma.sync.aligned.m16n8k16.row.col.f32.f16.f16.f32 "
        "{%0,%1,%2,%3}, {%4,%5,%6,%7}, {%8,%9}, {%0,%1,%2,%3};"
        : "+f"(c[0]), "+f"(c[1]), "+f"(c[2]), "+f"(c[3])
        : "r"(a[0]), "r"(a[1]), "r"(a[2]), "r"(a[3]), "r"(b0), "r"(b1));
}

// ------------------------------ prep kernels --------------------------------

// zero ungated (row, tile) output blocks; block 0 also zeroes g_cnt
__global__ void zero_ungated(const int* __restrict__ gate,
                             float* __restrict__ out) {
    int bid = blockIdx.x;            // 16384 = 4096 rows * 4 tiles
    if (bid == 0 && threadIdx.x < 4) g_cnt[threadIdx.x] = 0;
    int r = bid >> 2, t = bid & 3;
    if (gate[r * 4 + t] != 0) return;
    float4 z = {0.f, 0.f, 0.f, 0.f};
    reinterpret_cast<float4*>(out + (size_t)r * NDIM + t * 1024)[threadIdx.x] = z;
}

// sign(W) -> fp16, tiled [nb][kblk] 16KB stages; row r, 16B chunk c at c^(r&7)
__global__ void sign_w(const float* __restrict__ w) {
    size_t idx = (size_t)blockIdx.x * blockDim.x + threadIdx.x;  // *8 elems
    int row = (int)(idx >> 9);
    int k0  = ((int)idx & 511) * 8;
    const float4* p = reinterpret_cast<const float4*>(w + (size_t)row * KDIM + k0);
    float4 v0 = p[0], v1 = p[1];
    float f[8] = {v0.x, v0.y, v0.z, v0.w, v1.x, v1.y, v1.z, v1.w};
    __half s[8];
#pragma unroll
    for (int j = 0; j < 8; j++)
        s[j] = __float2half_rn((f[j] > 0.f) ? 1.f : ((f[j] < 0.f) ? -1.f : 0.f));
    int nb = row >> 7, r = row & 127, kblk = k0 >> 6;
    int c = (k0 & 63) >> 3;
    size_t off = (((size_t)(nb * 64 + kblk)) << 14) +
                 (size_t)r * 128 + ((size_t)(c ^ (r & 7)) << 4);
    *reinterpret_cast<uint4*>(g_Wt + off) = *reinterpret_cast<uint4*>(s);
}

// gated row compaction (order irrelevant)
__global__ void compact_gate(const int* __restrict__ gate) {
    int r = blockIdx.x * blockDim.x + threadIdx.x;
    if (r >= MDIM) return;
#pragma unroll
    for (int t = 0; t < 4; t++) {
        if (gate[r * 4 + t] != 0) {
            int pos = atomicAdd(&g_cnt[t], 1);
            g_rows[t][pos] = r;
        }
    }
}

// fused gather+quant: read gated x rows (f32), write fp16 swizzled A tiles.
// chunk (t, mblk128) = 1MB = [kblk 0..63] x (128 rows x 128B), chunk c^(r&7).
// grid (32 mblk128, 4 t, 8 kg).
__global__ __launch_bounds__(256) void gather_quant(const float* __restrict__ x) {
    int mblk = blockIdx.x, t = blockIdx.y, kg = blockIdx.z;
    int cnt = g_cnt[t];
    if (mblk * 128 >= cnt) return;
    __shared__ int srow[128];
    int tid = threadIdx.x;
    if (tid < 128) {
        int gidx = mblk * 128 + tid;
        srow[tid] = (gidx < cnt) ? g_rows[t][gidx] : g_rows[t][0];
    }
    __syncthreads();
    size_t base = ((size_t)(t * 32 + mblk)) << 20;
    int r = tid >> 3, c = tid & 7;            // 32 rows x 8 chunks / pass
#pragma unroll
    for (int kb = 0; kb < 8; kb++) {
        int kblk = kg * 8 + kb;
        size_t db = base + ((size_t)kblk << 14);
#pragma unroll
        for (int rp = 0; rp < 4; rp++) {
            int rr = r + rp * 32;
            const float4* src = reinterpret_cast<const float4*>(
                x + (size_t)srow[rr] * KDIM + kblk * 64 + c * 8);
            float4 v0 = src[0], v1 = src[1];
            __half h[8];
            h[0] = __float2half_rn(v0.x); h[1] = __float2half_rn(v0.y);
            h[2] = __float2half_rn(v0.z); h[3] = __float2half_rn(v0.w);
            h[4] = __float2half_rn(v1.x); h[5] = __float2half_rn(v1.y);
            h[6] = __float2half_rn(v1.z); h[7] = __float2half_rn(v1.w);
            size_t dd = db + (size_t)rr * 128 + ((size_t)(c ^ (rr & 7)) << 4);
            *reinterpret_cast<uint4*>(g_At + dd) = *reinterpret_cast<uint4*>(h);
        }
    }
}

// ------------------------------ GEMM kernel ---------------------------------
// grid (8 nblk, 16 mblk, 4 t), 256 threads, warp grid 4(M) x 2(N), warp 64x64.
// Block tile 256(M) x 128(N); stage = A chunk0 16K | A chunk1 16K | B 16K.

__global__ __launch_bounds__(256, 1) void trix_hmma(
    const float* __restrict__ scales,
    float* __restrict__ out) {
    const int t = blockIdx.z, mblk = blockIdx.y, nblk = blockIdx.x;
    const int cnt = g_cnt[t];
    if (mblk * 256 >= cnt) return;

    extern __shared__ char smem[];
    const uint32_t sb = smem_u32(smem);
    const int tid = threadIdx.x;
    const int warp = tid >> 5, lane = tid & 31;
    const int wm = warp >> 1, wn = warp & 1;     // 4(M) x 2(N)
    const int n0 = t * 1024 + nblk * 128;
    const int nb = t * 8 + nblk;

    if (tid < 128)
        reinterpret_cast<float*>(smem + SMEM_SC)[tid] = scales[n0 + tid];
    if (tid == 0) {
#pragma unroll
        for (int s = 0; s < STAGES; s++) {
            mbar_init(sb + 8u * s, 1);        // full: TMA tx
            mbar_init(sb + 24u + 8u * s, 8);  // empty: 8 warp arrivals
        }
    }
    __syncthreads();

    const unsigned char* aSrc = g_At + (((size_t)(t * 32 + mblk * 2)) << 20);
    const unsigned char* bSrc = g_Wt + ((size_t)nb << 20);

    auto fill = [&](int s, int kt) {
        uint32_t mb = sb + 8u * s;
        uint32_t st = sb + SMEM_ST + s * STAGE_BYTES;
        mbar_expect_tx(mb, STAGE_BYTES);
        bulk_g2s(st,         aSrc + ((size_t)kt << 14),                16384, mb);
        bulk_g2s(st + 16384, aSrc + (1u << 20) + ((size_t)kt << 14),   16384, mb);
        bulk_g2s(st + 32768, bSrc + ((size_t)kt << 14),                16384, mb);
    };
    const bool prod = (warp == 0) && elect_one();
    if (prod) {
#pragma unroll
        for (int s = 0; s < STAGES; s++) fill(s, s);
    }

    // ldmatrix addressing; A row r (0..255): chunk r>>7, byte (r&127)*128
    int aR[4], bR[4];
#pragma unroll
    for (int ms = 0; ms < 4; ms++) aR[ms] = wm * 64 + ms * 16 + (lane & 15);
    const int aCadd = lane >> 4;
#pragma unroll
    for (int nq = 0; nq < 4; nq++)
        bR[nq] = wn * 64 + nq * 16 + (lane & 7) + ((lane >> 4) << 3);
    const int bCadd = (lane >> 3) & 1;

    float d[4][8][4];
#pragma unroll
    for (int a = 0; a < 4; a++)
#pragma unroll
        for (int b = 0; b < 8; b++)
#pragma unroll
            for (int c = 0; c < 4; c++) d[a][b][c] = 0.f;

    for (int kt = 0; kt < NKT; kt++) {
        const int s = kt % 3;
        const uint32_t ph = (uint32_t)((kt / 3) & 1);
        mbar_wait(sb + 8u * s, ph);                       // data ready
        const uint32_t st = sb + SMEM_ST + s * STAGE_BYTES;
#pragma unroll
        for (int ks = 0; ks < 4; ks++) {
            uint32_t a[4][4], bf[4][4];
#pragma unroll
            for (int ms = 0; ms < 4; ms++) {
                uint32_t off = (uint32_t)(aR[ms] & 127) * 128 +
                               ((uint32_t)(aR[ms] >> 7) << 14) +
                               (((ks * 2 + aCadd) ^ (aR[ms] & 7)) << 4);
                ldm_x4(a[ms], st + off);
            }
#pragma unroll
            for (int nq = 0; nq < 4; nq++) {
                uint32_t off = bR[nq] * 128 +
                               (((ks * 2 + bCadd) ^ (bR[nq] & 7)) << 4);
                ldm_x4(bf[nq], st + 32768 + off);
            }
#pragma unroll
            for (int ms = 0; ms < 4; ms++)
#pragma unroll
                for (int nq = 0; nq < 4; nq++) {
                    hmma(d[ms][nq * 2],     a[ms], bf[nq][0], bf[nq][1]);
                    hmma(d[ms][nq * 2 + 1], a[ms], bf[nq][2], bf[nq][3]);
                }
        }
        if (elect_one()) mbar_arrive(sb + 24u + 8u * s);  // warp consumed
        if (prod && kt + STAGES < NKT) {
            mbar_wait(sb + 24u + 8u * s, ph);             // all 8 consumed
            fill(s, kt + STAGES);
        }
    }

    // epilogue: out = acc * scales[col] for gated rows
    const float* sSc = reinterpret_cast<const float*>(smem + SMEM_SC);
#pragma unroll
    for (int ms = 0; ms < 4; ms++) {
#pragma unroll
        for (int half = 0; half < 2; half++) {
            int gidx = mblk * 256 + wm * 64 + ms * 16 + (lane >> 2) + half * 8;
            if (gidx >= cnt) continue;
            int row = g_rows[t][gidx];
            float* orow = out + (size_t)row * NDIM + n0;
#pragma unroll
            for (int ns = 0; ns < 8; ns++) {
                int col = wn * 64 + ns * 8 + (lane & 3) * 2;
                float2 v;
                v.x = d[ms][ns][half * 2]     * sSc[col];
                v.y = d[ms][ns][half * 2 + 1] * sSc[col + 1];
                *reinterpret_cast<float2*>(orow + col) = v;
            }
        }
    }
}

// ------------------------------ launch --------------------------------------

extern "C" void kernel_launch(void* const* d_in, const int* in_sizes, int n_in,
                              void* d_out, int out_size) {
    const float* x      = (const float*)d_in[0];
    const int*   gate   = (const int*)d_in[1];
    const float* weight = (const float*)d_in[2];
    const float* scales = (const float*)d_in[3];
    float* out = (float*)d_out;

    cudaFuncSetAttribute(trix_hmma,
                         cudaFuncAttributeMaxDynamicSharedMemorySize, SMEM_TOTAL);

    zero_ungated<<<MDIM * 4, 256>>>(gate, out);
    sign_w<<<(int)((size_t)NDIM * KDIM / 8 / 256), 256>>>(weight);
    compact_gate<<<MDIM / 512, 512>>>(gate);
    gather_quant<<<dim3(32, 4, 8), 256>>>(x);
    trix_hmma<<<dim3(8, 16, 4), 256, SMEM_TOTAL>>>(scales, out);
}